// round 1
// baseline (speedup 1.0000x reference)
#include <cuda_runtime.h>

// Problem constants (fixed by the dataset; guarded at runtime).
#define NN 100000
#define EE 3200000
#define FF 128
#define F4 (FF / 4)   // 32 float4 per feature row
#define NWARPS 8      // warps (nodes) per block in SpMM

// ---------------- static scratch (no allocations allowed) ----------------
__device__ int   g_deg[NN];
__device__ float g_dinv[NN];
__device__ int   g_rowptr[NN + 1];
__device__ int   g_curptr[NN];
__device__ int   g_scanbuf[NN];
__device__ int   g_part[256];
__device__ int2  g_meta[EE];                 // (src_row, weight bits), CSR by dest
__device__ float4 g_buf0[NN * F4];           // P-buffer rotation (3 bufs: no aliasing)
__device__ float4 g_buf1[NN * F4];
__device__ float4 g_buf2[NN * F4];

// ---------------- CSR build ----------------
__global__ void hist_k(const int* __restrict__ col, int E) {
    int e = blockIdx.x * blockDim.x + threadIdx.x;
    if (e < E) atomicAdd(&g_deg[col[e]], 1);
}

__global__ void dinv_k(int n) {
    int i = blockIdx.x * blockDim.x + threadIdx.x;
    if (i < n) {
        int d = g_deg[i];
        g_dinv[i] = (d > 0) ? rsqrtf((float)d) : 0.0f;
    }
}

// Block-level inclusive scan (1024 elems/block) + block sums.
__global__ void scan1_k(int n) {
    __shared__ int sh[1024];
    int tid = threadIdx.x;
    int i = blockIdx.x * 1024 + tid;
    int v = (i < n) ? g_deg[i] : 0;
    sh[tid] = v;
    __syncthreads();
    for (int off = 1; off < 1024; off <<= 1) {
        int t = (tid >= off) ? sh[tid - off] : 0;
        __syncthreads();
        sh[tid] += t;
        __syncthreads();
    }
    if (i < n) g_scanbuf[i] = sh[tid];
    if (tid == 1023) g_part[blockIdx.x] = sh[1023];
}

// Exclusive scan of block sums (<=256 of them): single thread, trivial cost.
__global__ void scan2_k(int nb) {
    int s = 0;
    for (int b = 0; b < nb; b++) {
        int v = g_part[b];
        g_part[b] = s;
        s += v;
    }
}

__global__ void scan3_k(int n, int E) {
    int i = blockIdx.x * blockDim.x + threadIdx.x;
    if (i < n) {
        int excl = g_scanbuf[i] - g_deg[i] + g_part[i >> 10];
        g_rowptr[i] = excl;
        g_curptr[i] = excl;
    }
    if (i == 0) g_rowptr[n] = E;
}

__global__ void scatter_k(const int* __restrict__ row, const int* __restrict__ col, int E) {
    int e = blockIdx.x * blockDim.x + threadIdx.x;
    if (e < E) {
        int c = col[e];
        int r = row[e];
        int pos = atomicAdd(&g_curptr[c], 1);
        float w = g_dinv[r] * g_dinv[c];
        g_meta[pos] = make_int2(r, __float_as_int(w));
    }
}

// ---------------- fused SpMM + Chebyshev recurrence + output accumulate ----------------
// Warp-per-destination-node. s = prop(h)[c]. Then:
//   step==1: P1 = s;          acc  = mf[0]*x + w1*P1
//   step>=2: Pi = 2s - P_{i-2}; acc += wi*Pi
// wi = lap[step-1] * mf[step].
__global__ void __launch_bounds__(NWARPS * 32)
spmm_k(const float4* __restrict__ h,
       const float4* __restrict__ pprev2,
       float4* __restrict__ pout,
       float4* __restrict__ acc,
       const float* __restrict__ mf,
       const float* __restrict__ lap,
       int step, int K, int n) {
    __shared__ int2 smeta[NWARPS][32];
    int wid = threadIdx.x >> 5;
    int lane = threadIdx.x & 31;
    int c = blockIdx.x * NWARPS + wid;
    if (c >= n) return;

    int start = g_rowptr[c];
    int end   = g_rowptr[c + 1];

    float sx = 0.f, sy = 0.f, sz = 0.f, sw = 0.f;

    for (int base = start; base < end; base += 32) {
        int m = end - base;
        if (m > 32) m = 32;
        if (lane < m) smeta[wid][lane] = g_meta[base + lane];
        __syncwarp();
        #pragma unroll 4
        for (int k = 0; k < m; k++) {
            int2 mt = smeta[wid][k];
            float w = __int_as_float(mt.y);
            float4 hv = __ldg(&h[(long)mt.x * F4 + lane]);
            sx += w * hv.x;
            sy += w * hv.y;
            sz += w * hv.z;
            sw += w * hv.w;
        }
        __syncwarp();
    }

    long idx = (long)c * F4 + lane;
    float wi = lap[step - 1] * mf[step];

    if (step == 1) {
        float w0 = mf[0];
        float4 xv = h[idx];          // h == x at step 1
        float4 a;
        a.x = w0 * xv.x + wi * sx;
        a.y = w0 * xv.y + wi * sy;
        a.z = w0 * xv.z + wi * sz;
        a.w = w0 * xv.w + wi * sw;
        acc[idx]  = a;
        pout[idx] = make_float4(sx, sy, sz, sw);
    } else {
        float4 p2 = pprev2[idx];
        float px = 2.f * sx - p2.x;
        float py = 2.f * sy - p2.y;
        float pz = 2.f * sz - p2.z;
        float pw = 2.f * sw - p2.w;
        float4 a = acc[idx];
        a.x += wi * px;
        a.y += wi * py;
        a.z += wi * pz;
        a.w += wi * pw;
        acc[idx] = a;
        if (step < K) pout[idx] = make_float4(px, py, pz, pw);
    }
}

// ---------------- launch ----------------
extern "C" void kernel_launch(void* const* d_in, const int* in_sizes, int n_in,
                              void* d_out, int out_size) {
    const float* x   = (const float*)d_in[0];
    const float* mf  = (const float*)d_in[1];   // (1, K+1, 1) -> K+1 floats
    const float* lap = (const float*)d_in[2];   // (K+1,)
    const int*   ei  = (const int*)d_in[3];     // (2, E) row-major

    int E = in_sizes[3] / 2;
    int K = in_sizes[2] - 1;
    int n = in_sizes[0] / FF;
    if (n > NN) n = NN;
    if (E > EE) E = EE;

    const int* rowp = ei;
    const int* colp = ei + E;
    float4* out = (float4*)d_out;

    void* degp;
    cudaGetSymbolAddress(&degp, g_deg);
    cudaMemsetAsync(degp, 0, (size_t)n * sizeof(int));

    int tb = 256;
    hist_k<<<(E + tb - 1) / tb, tb>>>(colp, E);
    dinv_k<<<(n + tb - 1) / tb, tb>>>(n);
    int nb = (n + 1023) / 1024;
    scan1_k<<<nb, 1024>>>(n);
    scan2_k<<<1, 1>>>(nb);
    scan3_k<<<(n + tb - 1) / tb, tb>>>(n, E);
    scatter_k<<<(E + tb - 1) / tb, tb>>>(rowp, colp, E);

    void *p0, *p1, *p2v;
    cudaGetSymbolAddress(&p0, g_buf0);
    cudaGetSymbolAddress(&p1, g_buf1);
    cudaGetSymbolAddress(&p2v, g_buf2);
    float4* bufs[3] = {(float4*)p0, (float4*)p1, (float4*)p2v};

    int grid = (n + NWARPS - 1) / NWARPS;
    const float4* h = (const float4*)x;        // P0
    const float4* pprev2 = (const float4*)x;   // unused at step 1

    for (int step = 1; step <= K; step++) {
        float4* pout = bufs[(step - 1) % 3];
        spmm_k<<<grid, NWARPS * 32>>>(h, pprev2, pout, out, mf, lap, step, K, n);
        pprev2 = h;
        h = pout;
    }
}

// round 2
// speedup vs baseline: 1.0329x; 1.0329x over previous
#include <cuda_runtime.h>

// Problem constants (fixed by the dataset; guarded at runtime).
#define NN 100000
#define EE 3200000
#define FF 128
#define F4 (FF / 4)   // 32 float4 per feature row
#define NWARPS 8      // warps (dest nodes) per block in SpMM

// ---------------- static scratch (no allocations allowed) ----------------
__device__ int    g_deg[NN];
__device__ float  g_dinv[NN];
__device__ int    g_rowptr[NN + 1];
__device__ int    g_curptr[NN];
__device__ int    g_scanbuf[NN];
__device__ int    g_part[256];
__device__ int    g_meta[EE];                 // src row only (scaled space), CSR by dest
__device__ float4 g_buf0[NN * F4];            // P'-buffer rotation
__device__ float4 g_buf1[NN * F4];
__device__ float4 g_buf2[NN * F4];            // holds X' = Dinv*x initially

// ---------------- CSR build ----------------
__global__ void zero_k(int n) {
    int i = blockIdx.x * blockDim.x + threadIdx.x;
    if (i < n) g_deg[i] = 0;
}

__global__ void hist_k(const int* __restrict__ col, int E) {
    int e = blockIdx.x * blockDim.x + threadIdx.x;
    if (e < E) atomicAdd(&g_deg[col[e]], 1);
}

// Block-level inclusive scan (1024/block) + block sums + dinv.
__global__ void scan1_k(int n) {
    __shared__ int sh[1024];
    int tid = threadIdx.x;
    int i = blockIdx.x * 1024 + tid;
    int v = (i < n) ? g_deg[i] : 0;
    if (i < n) g_dinv[i] = (v > 0) ? rsqrtf((float)v) : 0.0f;
    sh[tid] = v;
    __syncthreads();
    for (int off = 1; off < 1024; off <<= 1) {
        int t = (tid >= off) ? sh[tid - off] : 0;
        __syncthreads();
        sh[tid] += t;
        __syncthreads();
    }
    if (i < n) g_scanbuf[i] = sh[tid];
    if (tid == 1023) g_part[blockIdx.x] = sh[1023];
}

// Fused: finish scan (rowptr/curptr) + prescale X' = Dinv * x into g_buf2.
__global__ void finalize_k(const float4* __restrict__ x4, int n, int E, int nb) {
    int gid = blockIdx.x * blockDim.x + threadIdx.x;

    if (gid < n) {
        int blk = gid >> 10;
        int pre = 0;
        for (int b = 0; b < blk; b++) pre += g_part[b];  // small uniform loop, L1-cached
        int excl = g_scanbuf[gid] - g_deg[gid] + pre;
        g_rowptr[gid] = excl;
        g_curptr[gid] = excl;
        if (gid == 0) g_rowptr[n] = E;
    }

    int total = n * F4;
    for (int j = gid; j < total; j += gridDim.x * blockDim.x) {
        float s = g_dinv[j >> 5];
        float4 v = x4[j];
        v.x *= s; v.y *= s; v.z *= s; v.w *= s;
        g_buf2[j] = v;
    }
}

__global__ void scatter_k(const int* __restrict__ row, const int* __restrict__ col, int E) {
    int e = blockIdx.x * blockDim.x + threadIdx.x;
    if (e < E) {
        int c = col[e];
        int pos = atomicAdd(&g_curptr[c], 1);
        g_meta[pos] = row[e];
    }
}

// ---------------- fused SpMM + scaled Chebyshev recurrence + output ----------------
// Scaled space: P'_i = Dinv * P_i. Gather is UNWEIGHTED:
//   S[c] = sum_{e->c} h[src_e]          (h = P'_{i-1})
//   step 1:  P'_1 = dinv2 * S;                acc = mf0*X' + w1*P'_1
//   step>=2: P'_i = 2*dinv2*S - P'_{i-2};     acc += wi*P'_i
//   step K:  out = acc * sqrt(deg)   (deg==0 handled analytically)
__global__ void __launch_bounds__(NWARPS * 32)
spmm_k(const float4* __restrict__ h,
       const float4* __restrict__ pprev2,
       float4* __restrict__ pout,
       float4* __restrict__ acc,
       const float4* __restrict__ x4,
       const float* __restrict__ mf,
       const float* __restrict__ lap,
       int step, int K, int n) {
    __shared__ int smeta[NWARPS][32];
    int wid = threadIdx.x >> 5;
    int lane = threadIdx.x & 31;
    int c = blockIdx.x * NWARPS + wid;
    if (c >= n) return;

    int start = g_rowptr[c];
    int end   = g_rowptr[c + 1];

    float sx = 0.f, sy = 0.f, sz = 0.f, sw = 0.f;

    for (int base = start; base < end; base += 32) {
        int m = end - base;
        if (m > 32) m = 32;
        if (lane < m) smeta[wid][lane] = g_meta[base + lane];
        __syncwarp();
        #pragma unroll 4
        for (int k = 0; k < m; k++) {
            int r = smeta[wid][k];
            float4 hv = __ldg(&h[(long)r * F4 + lane]);
            sx += hv.x;
            sy += hv.y;
            sz += hv.z;
            sw += hv.w;
        }
        __syncwarp();
    }

    long idx = (long)c * F4 + lane;
    float dinv = g_dinv[c];
    float d2 = dinv * dinv;
    float wi = lap[step - 1] * mf[step];

    if (step == 1) {
        float w0 = mf[0];
        float4 xp = h[idx];          // h == X' at step 1
        float4 p;
        p.x = d2 * sx; p.y = d2 * sy; p.z = d2 * sz; p.w = d2 * sw;
        float4 a;
        a.x = w0 * xp.x + wi * p.x;
        a.y = w0 * xp.y + wi * p.y;
        a.z = w0 * xp.z + wi * p.z;
        a.w = w0 * xp.w + wi * p.w;
        __stcs(&acc[idx], a);
        pout[idx] = p;
    } else {
        float4 p2 = __ldcs(&pprev2[idx]);
        float td2 = 2.f * d2;
        float4 p;
        p.x = td2 * sx - p2.x;
        p.y = td2 * sy - p2.y;
        p.z = td2 * sz - p2.z;
        p.w = td2 * sw - p2.w;
        float4 a = __ldcs(&acc[idx]);
        a.x += wi * p.x;
        a.y += wi * p.y;
        a.z += wi * p.z;
        a.w += wi * p.w;
        if (step < K) {
            __stcs(&acc[idx], a);
            pout[idx] = p;           // next step's gather source: keep cacheable
        } else {
            int deg = g_deg[c];
            if (deg > 0) {
                float sd = sqrtf((float)deg);
                a.x *= sd; a.y *= sd; a.z *= sd; a.w *= sd;
                acc[idx] = a;
            } else {
                // P_{2j} = (-1)^j x, P_odd = 0 at isolated (in-deg 0) nodes
                float cE = mf[0];
                float sgn = -1.f;
                for (int j = 2; j <= K; j += 2) {
                    cE += sgn * lap[j - 1] * mf[j];
                    sgn = -sgn;
                }
                float4 xv = x4[idx];
                xv.x *= cE; xv.y *= cE; xv.z *= cE; xv.w *= cE;
                acc[idx] = xv;
            }
        }
    }
}

// ---------------- launch ----------------
extern "C" void kernel_launch(void* const* d_in, const int* in_sizes, int n_in,
                              void* d_out, int out_size) {
    const float* x   = (const float*)d_in[0];
    const float* mf  = (const float*)d_in[1];   // (1, K+1, 1) -> K+1 floats
    const float* lap = (const float*)d_in[2];   // (K+1,)
    const int*   ei  = (const int*)d_in[3];     // (2, E) row-major

    int E = in_sizes[3] / 2;
    int K = in_sizes[2] - 1;
    int n = in_sizes[0] / FF;
    if (n > NN) n = NN;
    if (E > EE) E = EE;

    const int* rowp = ei;
    const int* colp = ei + E;
    float4* out = (float4*)d_out;
    const float4* x4 = (const float4*)x;

    int tb = 256;
    int nb = (n + 1023) / 1024;

    // Exactly 5 launches before spmm so ncu -s 5 -c 1 captures an spmm step.
    zero_k<<<(n + tb - 1) / tb, tb>>>(n);
    hist_k<<<(E + tb - 1) / tb, tb>>>(colp, E);
    scan1_k<<<nb, 1024>>>(n);
    finalize_k<<<(n * F4 + tb - 1) / tb, tb>>>(x4, n, E, nb);
    scatter_k<<<(E + tb - 1) / tb, tb>>>(rowp, colp, E);

    void *p0, *p1, *p2v;
    cudaGetSymbolAddress(&p0, g_buf0);
    cudaGetSymbolAddress(&p1, g_buf1);
    cudaGetSymbolAddress(&p2v, g_buf2);
    float4* bufs[3] = {(float4*)p0, (float4*)p1, (float4*)p2v};

    int grid = (n + NWARPS - 1) / NWARPS;
    const float4* h = (const float4*)p2v;       // X' = Dinv*x  (== P'_0)
    const float4* pprev2 = (const float4*)p2v;  // unused at step 1

    for (int step = 1; step <= K; step++) {
        float4* pout = bufs[(step - 1) % 3];
        spmm_k<<<grid, NWARPS * 32>>>(h, pprev2, pout, out, x4, mf, lap, step, K, n);
        pprev2 = h;
        h = (const float4*)pout;
    }
}

// round 3
// speedup vs baseline: 1.2514x; 1.2116x over previous
#include <cuda_runtime.h>
#include <cuda_fp16.h>

// Problem constants (fixed by the dataset; guarded at runtime).
#define NN 100000
#define EE 3200000
#define FF 128
#define F4 (FF / 4)   // 32 float4 per feature row
#define NWARPS 8      // warps (dest nodes) per block in SpMM

// ---------------- static scratch (no allocations; zero-init at load) ------
__device__ int    g_deg[NN];                  // re-zeroed at end of each call
__device__ float  g_dinv[NN];
__device__ float  g_sqd[NN];
__device__ int    g_rowptr[NN + 1];
__device__ int    g_curptr[NN];
__device__ int    g_meta[EE];                 // src row, CSR by dest
__device__ float4 g_px[NN * F4];              // X' = Dinv*x (fp32 master, P0)
__device__ float4 g_pa[NN * F4];              // fp32 P ping-pong (odd steps)
__device__ float4 g_pb[NN * F4];              // fp32 P ping-pong (even steps)
__device__ uint2  g_h16a[NN * F4];            // fp16 gather ping-pong
__device__ uint2  g_h16b[NN * F4];

// ---------------- setup kernel 1: in-degree histogram ----------------
__global__ void hist_k(const int* __restrict__ col, int E) {
    int e = blockIdx.x * blockDim.x + threadIdx.x;
    if (e < E) atomicAdd(&g_deg[col[e]], 1);
}

// ---------------- setup kernel 2: single-block scan + dinv/sqd ------------
__global__ void scan_k(int n, int E) {
    __shared__ int warpsum[32];
    __shared__ int carry;
    int tid = threadIdx.x, lane = tid & 31, w = tid >> 5;
    if (tid == 0) carry = 0;
    __syncthreads();
    for (int base = 0; base < n; base += 1024) {
        int i = base + tid;
        int v = (i < n) ? g_deg[i] : 0;
        if (i < n) {
            g_dinv[i] = (v > 0) ? rsqrtf((float)v) : 0.0f;
            g_sqd[i]  = (v > 0) ? sqrtf((float)v)  : 0.0f;
        }
        int s = v;
        #pragma unroll
        for (int o = 1; o < 32; o <<= 1) {
            int t = __shfl_up_sync(0xffffffffu, s, o);
            if (lane >= o) s += t;
        }
        if (lane == 31) warpsum[w] = s;
        __syncthreads();
        if (w == 0) {
            int ws = warpsum[lane];
            #pragma unroll
            for (int o = 1; o < 32; o <<= 1) {
                int t = __shfl_up_sync(0xffffffffu, ws, o);
                if (lane >= o) ws += t;
            }
            warpsum[lane] = ws;
        }
        __syncthreads();
        int pre = carry + ((w > 0) ? warpsum[w - 1] : 0);
        int excl = pre + s - v;
        if (i < n) { g_rowptr[i] = excl; g_curptr[i] = excl; }
        __syncthreads();
        if (tid == 1023) carry += warpsum[31];
        __syncthreads();
    }
    if (tid == 0) g_rowptr[n] = E;
}

// ---------------- setup kernel 3: scatter + prescale X' + re-zero deg -----
__global__ void scatter_k(const int* __restrict__ row, const int* __restrict__ col,
                          const float4* __restrict__ x4, int E, int n) {
    int gid = blockIdx.x * blockDim.x + threadIdx.x;
    int stride = gridDim.x * blockDim.x;

    if (gid < E) {
        int c = col[gid];
        int pos = atomicAdd(&g_curptr[c], 1);
        g_meta[pos] = row[gid];
    }

    int total = n * F4;
    for (int j = gid; j < total; j += stride) {
        float s = g_dinv[j >> 5];
        float4 v = x4[j];
        v.x *= s; v.y *= s; v.z *= s; v.w *= s;
        g_px[j] = v;
        __half2 h01 = __floats2half2_rn(v.x, v.y);
        __half2 h23 = __floats2half2_rn(v.z, v.w);
        uint2 u;
        u.x = *(unsigned int*)&h01;
        u.y = *(unsigned int*)&h23;
        g_h16a[j] = u;
    }

    for (int j = gid; j < n; j += stride) g_deg[j] = 0;   // ready for next call
}

// ---------------- fused SpMM (fp16 gather) + scaled Chebyshev + output ----
// Scaled space: P'_i = Dinv * P_i; gather is unweighted sum over in-edges.
//   step 1:  P'_1 = d2*S;              acc = mf0*X' + w1*P'_1
//   step>=2: P'_i = 2*d2*S - P'_{i-2}; acc += wi*P'_i
//   step K:  out = acc * sqrt(deg); isolated nodes handled analytically.
__global__ void __launch_bounds__(NWARPS * 32)
spmm_k(const uint2*  __restrict__ h16,     // fp16 P'_{i-1} (gather source)
       const float4* __restrict__ pprev2,  // fp32 P'_{i-2} (X' at step 1/2)
       float4*       pout,                 // fp32 P'_i (may alias pprev2, RMW per-thread)
       uint2*        __restrict__ pout16,  // fp16 P'_i
       float4*       __restrict__ acc,
       const float4* __restrict__ x4,
       const float*  __restrict__ mf,
       const float*  __restrict__ lap,
       int step, int K, int n) {
    __shared__ int smeta[NWARPS][32];
    int wid = threadIdx.x >> 5;
    int lane = threadIdx.x & 31;
    int c = blockIdx.x * NWARPS + wid;
    if (c >= n) return;

    int start = g_rowptr[c];
    int end   = g_rowptr[c + 1];

    float sx = 0.f, sy = 0.f, sz = 0.f, sw = 0.f;

    for (int base = start; base < end; base += 32) {
        int m = end - base;
        if (m > 32) m = 32;
        if (lane < m) smeta[wid][lane] = g_meta[base + lane];
        __syncwarp();
        #pragma unroll 8
        for (int k = 0; k < m; k++) {
            int r = smeta[wid][k];
            uint2 hv = __ldg(&h16[r * F4 + lane]);
            float2 fa = __half22float2(*(const __half2*)&hv.x);
            float2 fb = __half22float2(*(const __half2*)&hv.y);
            sx += fa.x; sy += fa.y; sz += fb.x; sw += fb.y;
        }
        __syncwarp();
    }

    int idx = c * F4 + lane;
    float dinv = g_dinv[c];
    float d2 = dinv * dinv;
    float wi = lap[step - 1] * mf[step];

    float4 p;
    float4 a;
    if (step == 1) {
        float w0 = mf[0];
        float4 xp = pprev2[idx];              // X'
        p.x = d2 * sx; p.y = d2 * sy; p.z = d2 * sz; p.w = d2 * sw;
        a.x = w0 * xp.x + wi * p.x;
        a.y = w0 * xp.y + wi * p.y;
        a.z = w0 * xp.z + wi * p.z;
        a.w = w0 * xp.w + wi * p.w;
    } else {
        float4 p2 = pprev2[idx];
        float td2 = 2.f * d2;
        p.x = td2 * sx - p2.x;
        p.y = td2 * sy - p2.y;
        p.z = td2 * sz - p2.z;
        p.w = td2 * sw - p2.w;
        a = acc[idx];
        a.x += wi * p.x;
        a.y += wi * p.y;
        a.z += wi * p.z;
        a.w += wi * p.w;
    }

    if (step < K) {
        acc[idx]  = a;
        pout[idx] = p;
        __half2 h01 = __floats2half2_rn(p.x, p.y);
        __half2 h23 = __floats2half2_rn(p.z, p.w);
        uint2 u;
        u.x = *(unsigned int*)&h01;
        u.y = *(unsigned int*)&h23;
        pout16[idx] = u;
    } else {
        float sd = g_sqd[c];
        if (sd > 0.f) {
            a.x *= sd; a.y *= sd; a.z *= sd; a.w *= sd;
            acc[idx] = a;
        } else {
            // isolated node: P_{2j} = (-1)^j x, P_odd = 0
            float cE = mf[0];
            float sgn = -1.f;
            for (int j = 2; j <= K; j += 2) {
                cE += sgn * lap[j - 1] * mf[j];
                sgn = -sgn;
            }
            float4 xv = x4[idx];
            xv.x *= cE; xv.y *= cE; xv.z *= cE; xv.w *= cE;
            acc[idx] = xv;
        }
    }
}

// ---------------- launch ----------------
extern "C" void kernel_launch(void* const* d_in, const int* in_sizes, int n_in,
                              void* d_out, int out_size) {
    const float* x   = (const float*)d_in[0];
    const float* mf  = (const float*)d_in[1];   // (1, K+1, 1)
    const float* lap = (const float*)d_in[2];   // (K+1,)
    const int*   ei  = (const int*)d_in[3];     // (2, E) row-major

    int E = in_sizes[3] / 2;
    int K = in_sizes[2] - 1;
    int n = in_sizes[0] / FF;
    if (n > NN) n = NN;
    if (E > EE) E = EE;

    const int* rowp = ei;
    const int* colp = ei + E;
    float4* out = (float4*)d_out;
    const float4* x4 = (const float4*)x;

    int tb = 256;
    int scat_work = (E > n * F4) ? E : n * F4;

    // Exactly 3 setup launches; g_deg is zero on entry (static init / prev call).
    hist_k<<<(E + tb - 1) / tb, tb>>>(colp, E);
    scan_k<<<1, 1024>>>(n, E);
    scatter_k<<<(scat_work + tb - 1) / tb, tb>>>(rowp, colp, x4, E, n);

    void *px, *pa, *pb, *ha, *hb;
    cudaGetSymbolAddress(&px, g_px);
    cudaGetSymbolAddress(&pa, g_pa);
    cudaGetSymbolAddress(&pb, g_pb);
    cudaGetSymbolAddress(&ha, g_h16a);
    cudaGetSymbolAddress(&hb, g_h16b);

    float4* f32buf[2] = {(float4*)pb, (float4*)pa};   // step i -> f32buf[i&1]
    uint2*  h16buf[2] = {(uint2*)ha, (uint2*)hb};     // P_i (fp16) -> h16buf[i&1]

    int grid = (n + NWARPS - 1) / NWARPS;

    for (int step = 1; step <= K; step++) {
        const uint2* h16 = h16buf[(step - 1) & 1];     // P_{i-1}
        uint2* p16out    = h16buf[step & 1];
        float4* pout     = f32buf[step & 1];
        const float4* pprev2 =
            (step <= 2) ? (const float4*)px            // X' (P0) for steps 1,2
                        : (const float4*)f32buf[step & 1];  // same-parity buffer (RMW)
        spmm_k<<<grid, NWARPS * 32>>>(h16, pprev2, pout, p16out, out, x4,
                                      mf, lap, step, K, n);
    }
}